// round 12
// baseline (speedup 1.0000x reference)
#include <cuda_runtime.h>
#include <cuda_fp16.h>
#include <math.h>
#include <stdint.h>

#define NPIX 16384
#define TT 16

// ---------------- device scratch -------------------------------------------
__device__ float g_C  [NPIX*128];
__device__ float g_m  [NPIX*128];
__device__ float g_H32[NPIX*128];
__device__ float g_Y  [NPIX*640];               // vh|kh|qh|km|vm (fp32)
__device__ __half g_HAh[NPIX*128], g_HAl[NPIX*128];   // H ping (read step start)
__device__ __half g_HBh[NPIX*128], g_HBl[NPIX*128];   // H pong (written by lstm)
__device__ __half g_mh[NPIX*128],  g_ml[NPIX*128];
__device__ __half g_xTh[(size_t)TT*NPIX*128], g_xTl[(size_t)TT*NPIX*128];
__device__ __half g_W5h[5*128*128], g_W5l[5*128*128];     // [j][k][o]
__device__ __half g_W8h[8*256*128], g_W8l[8*256*128];     // [j][k][o]
__device__ __half g_W4h[256*512], g_W4l[256*512];         // conv10..13 interleaved
__device__ float g_b4[512];

__device__ __forceinline__ float sigmoidf_(float x){ return 1.f/(1.f+expf(-x)); }
__device__ __forceinline__ uint32_t smem_u32(const void* p){
    uint32_t a; asm("{ .reg .u64 t; cvta.to.shared.u64 t, %1; cvt.u32.u64 %0, t; }":"=r"(a):"l"(p)); return a;
}
__device__ __forceinline__ void store_hl(__half* Ph, __half* Pl, size_t off, float4 v){
    __half2 h01 = __floats2half2_rn(v.x, v.y);
    __half2 h23 = __floats2half2_rn(v.z, v.w);
    __half2 l01 = __floats2half2_rn(v.x - __low2float(h01), v.y - __high2float(h01));
    __half2 l23 = __floats2half2_rn(v.z - __low2float(h23), v.w - __high2float(h23));
    *(__half2*)(Ph+off) = h01; *(__half2*)(Ph+off+2) = h23;
    *(__half2*)(Pl+off) = l01; *(__half2*)(Pl+off+2) = l23;
}
__device__ __forceinline__ void store_hl1(__half* Ph, __half* Pl, size_t off, float v){
    __half h = __float2half_rn(v);
    Ph[off] = h;
    Pl[off] = __float2half_rn(v - __half2float(h));
}

#define LDSM4(r, a) asm volatile("ldmatrix.sync.aligned.m8n8.x4.shared.b16 {%0,%1,%2,%3}, [%4];" \
  : "=r"((r)[0]),"=r"((r)[1]),"=r"((r)[2]),"=r"((r)[3]) : "r"(a))
#define LDSM4T(r, a) asm volatile("ldmatrix.sync.aligned.m8n8.x4.trans.shared.b16 {%0,%1,%2,%3}, [%4];" \
  : "=r"((r)[0]),"=r"((r)[1]),"=r"((r)[2]),"=r"((r)[3]) : "r"(a))
#define MMA(d, a, b0_, b1_) asm volatile( \
  "mma.sync.aligned.m16n8k16.row.col.f32.f16.f16.f32 {%0,%1,%2,%3},{%4,%5,%6,%7},{%8,%9},{%0,%1,%2,%3};" \
  : "+f"((d)[0]),"+f"((d)[1]),"+f"((d)[2]),"+f"((d)[3]) \
  : "r"((a)[0]),"r"((a)[1]),"r"((a)[2]),"r"((a)[3]), "r"(b0_),"r"(b1_))
#define CPA(dst, src) asm volatile("cp.async.cg.shared.global [%0], [%1], 16;"::"r"(dst),"l"(src))
#define CPCOMMIT()    asm volatile("cp.async.commit_group;")
#define CPWAIT1()     asm volatile("cp.async.wait_group 1;")
#define CPWAIT0()     asm volatile("cp.async.wait_group 0;")

// gemm smem: A [2 stages][hi/lo][64][40]h = 20480B ; B [2][hi/lo][32][136]h = 34816B
#define SB_B     20480
#define SMEM_G2  55296

// ---------------- weight prep ----------------------------------------------
__global__ void k_wprep(const float* __restrict__ W5, const float* __restrict__ W8,
                        const float* __restrict__ b8){
    int idx = blockIdx.x*blockDim.x + threadIdx.x;
    if (idx < 81920){                                    // W5 -> k-major hi/lo
        int j = idx/16384, r = idx%16384, o = r/128, k = r%128;
        float v = W5[idx];
        __half h = __float2half_rn(v);
        g_W5h[(j*128 + k)*128 + o] = h;
        g_W5l[(j*128 + k)*128 + o] = __float2half_rn(v - __half2float(h));
        return;
    }
    int i2 = idx - 81920;
    if (i2 < 262144){                                    // W8 -> k-major hi/lo
        int j = i2/32768, r = i2%32768, o = r/256, k = r%256;
        float v = W8[i2];
        __half h = __float2half_rn(v);
        g_W8h[((size_t)j*256 + k)*128 + o] = h;
        g_W8l[((size_t)j*256 + k)*128 + o] = __float2half_rn(v - __half2float(h));
        return;
    }
    int i3 = i2 - 262144;
    if (i3 < 131072){                                    // conv10..13 interleave
        int k = i3 >> 9, n = i3 & 511;
        int jj = n & 3, c = n >> 2;
        float v = W8[(size_t)(4+jj)*32768 + c*256 + k];
        __half h = __float2half_rn(v);
        g_W4h[k*512 + n] = h;
        g_W4l[k*512 + n] = __float2half_rn(v - __half2float(h));
        return;
    }
    int i5 = i3 - 131072;
    if (i5 < 512){ g_b4[i5] = b8[(4 + (i5 & 3))*128 + (i5 >> 2)]; }
}

// ---------------------------------------------------------------------------
// gemm2: generic conv GEMM. 64-pixel x 128-out CTA tile, warp tile 32x32.
// ---------------------------------------------------------------------------
__global__ __launch_bounds__(256, 3)
void gemm2(const __half* __restrict__ A0h, const __half* __restrict__ A0l,
           const __half* __restrict__ A1h, const __half* __restrict__ A1l, int S,
           int K, const __half* __restrict__ Wh, const __half* __restrict__ Wl,
           const float* __restrict__ bias,
           float* __restrict__ outF, int outStride, int outColOff)
{
    extern __shared__ char smem[];
    const uint32_t sbase = smem_u32(smem);
    const int tid = threadIdx.x, wid = tid >> 5, lane = tid & 31;
    const int p0 = blockIdx.x * 64;
    const int j  = blockIdx.y;

    const int wm = wid >> 2, wn = wid & 3;
    const int m0 = wm*32, n0 = wn*32;
    const int l15 = lane & 15, lH = (lane >> 4) << 3;

    const __half* wbH = Wh + (size_t)j*K*128;
    const __half* wbL = Wl + (size_t)j*K*128;

    auto load_chunk = [&](int ch, int s){
        const int k0 = ch*32;
        const __half *srcH, *srcL; int koff;
        if (k0 < S){ srcH = A0h; srcL = A0l; koff = k0; }
        else       { srcH = A1h; srcL = A1l; koff = k0 - S; }
        #pragma unroll
        for (int q = tid; q < 512; q += 256){
            int h = q >> 8, e = q & 255, r = e >> 2, seg = e & 3;
            uint32_t dst = sbase + (uint32_t)((s*2 + h)*5120 + r*80 + seg*16);
            CPA(dst, (h ? srcL : srcH) + (size_t)(p0 + r)*128 + koff + seg*8);
        }
        #pragma unroll
        for (int q = tid; q < 1024; q += 256){
            int h = q >> 9, e = q & 511, r = e >> 4, seg = e & 15;
            uint32_t dst = sbase + SB_B + (uint32_t)((s*2 + h)*8704 + r*272 + seg*16);
            CPA(dst, (h ? wbL : wbH) + (size_t)(k0 + r)*128 + seg*8);
        }
    };

    float d[2][4][4];
    #pragma unroll
    for (int a=0;a<2;a++){
        #pragma unroll
        for (int b=0;b<4;b++){
            #pragma unroll
            for (int e=0;e<4;e++) d[a][b][e]=0.f; } }

    const int CH = K >> 5;
    load_chunk(0, 0); CPCOMMIT();
    if (CH > 1) load_chunk(1, 1);
    CPCOMMIT();

    for (int ch = 0; ch < CH; ch++){
        const int s = ch & 1;
        CPWAIT1();
        __syncthreads();
        #pragma unroll
        for (int ks = 0; ks < 2; ks++){
            const int k = ks*16;
            uint32_t AH[2][4], AL[2][4], BH[2][4], BL[2][4];
            #pragma unroll
            for (int mi = 0; mi < 2; mi++){
                uint32_t ad = sbase + (uint32_t)(s*10240 + ((m0 + mi*16 + l15)*40 + k + lH)*2);
                LDSM4(AH[mi], ad);
                LDSM4(AL[mi], ad + 5120);
            }
            #pragma unroll
            for (int bt = 0; bt < 2; bt++){
                uint32_t bd = sbase + SB_B + (uint32_t)(s*17408 + ((k + l15)*136 + n0 + bt*16 + lH)*2);
                LDSM4T(BH[bt], bd);
                LDSM4T(BL[bt], bd + 8704);
            }
            #pragma unroll
            for (int mi = 0; mi < 2; mi++){
                #pragma unroll
                for (int nj = 0; nj < 4; nj++){
                    const int t = nj >> 1, o = (nj & 1)*2;
                    MMA(d[mi][nj], AH[mi], BH[t][o], BH[t][o+1]);
                    MMA(d[mi][nj], AL[mi], BH[t][o], BH[t][o+1]);
                    MMA(d[mi][nj], AH[mi], BL[t][o], BL[t][o+1]);
                }
            }
        }
        __syncthreads();
        if (ch + 2 < CH) load_chunk(ch + 2, s);
        CPCOMMIT();
    }
    CPWAIT0();
    __syncthreads();

    float* sbuf = (float*)smem;
    #pragma unroll
    for (int h2 = 0; h2 < 2; h2++){
        __syncthreads();
        if (wm == h2){
            #pragma unroll
            for (int mi = 0; mi < 2; mi++){
                int r0 = mi*16 + (lane>>2);
                #pragma unroll
                for (int nj = 0; nj < 4; nj++){
                    int c = n0 + nj*8 + ((lane&3)<<1);
                    sbuf[r0*132 + c]       = d[mi][nj][0];
                    sbuf[r0*132 + c + 1]   = d[mi][nj][1];
                    sbuf[(r0+8)*132 + c]   = d[mi][nj][2];
                    sbuf[(r0+8)*132 + c+1] = d[mi][nj][3];
                }
            }
        }
        __syncthreads();
        for (int q = tid; q < 32*32; q += 256){
            int r = q >> 5, c4 = (q & 31) << 2;
            float4 v = *(float4*)&sbuf[r*132 + c4];
            float4 bv = *(const float4*)&bias[j*128 + c4];
            v.x += bv.x; v.y += bv.y; v.z += bv.z; v.w += bv.w;
            *(float4*)(outF + (size_t)(p0 + h2*32 + r)*outStride + outColOff + j*128 + c4) = v;
        }
    }
}

// ---------------------------------------------------------------------------
// gemm_step1: blockIdx.y<4 -> conv10..13 interleaved + fused LSTM gates
//             (reads H_A + x_t, writes H_B + g_C);
//             blockIdx.y in {4,5} -> conv4..5 on m -> g_Y[384 + (y-4)*128].
// ---------------------------------------------------------------------------
__global__ __launch_bounds__(256, 3)
void gemm_step1(const __half* __restrict__ Xh, const __half* __restrict__ Xl,
                const float* __restrict__ b5)
{
    extern __shared__ char smem[];
    const uint32_t sbase = smem_u32(smem);
    const int tid = threadIdx.x, wid = tid >> 5, lane = tid & 31;
    const int p0 = blockIdx.x * 64;
    const int yb = blockIdx.y;

    const int wm = wid >> 2, wn = wid & 3;
    const int m0 = wm*32, n0 = wn*32;
    const int l15 = lane & 15, lH = (lane >> 4) << 3;

    if (yb < 4){
        const int nb = yb;
        auto load_chunk = [&](int ch, int s){
            const int k0 = ch*32;
            const __half *srcH, *srcL; int koff;
            if (k0 < 128){ srcH = g_HAh; srcL = g_HAl; koff = k0; }
            else         { srcH = Xh;    srcL = Xl;    koff = k0 - 128; }
            #pragma unroll
            for (int q = tid; q < 512; q += 256){
                int h = q >> 8, e = q & 255, r = e >> 2, seg = e & 3;
                uint32_t dst = sbase + (uint32_t)((s*2 + h)*5120 + r*80 + seg*16);
                CPA(dst, (h ? srcL : srcH) + (size_t)(p0 + r)*128 + koff + seg*8);
            }
            #pragma unroll
            for (int q = tid; q < 1024; q += 256){
                int h = q >> 9, e = q & 511, r = e >> 4, seg = e & 15;
                uint32_t dst = sbase + SB_B + (uint32_t)((s*2 + h)*8704 + r*272 + seg*16);
                CPA(dst, (h ? g_W4l : g_W4h) + (size_t)(k0 + r)*512 + nb*128 + seg*8);
            }
        };

        float d[2][4][4];
        #pragma unroll
        for (int a=0;a<2;a++){
            #pragma unroll
            for (int b=0;b<4;b++){
                #pragma unroll
                for (int e=0;e<4;e++) d[a][b][e]=0.f; } }

        load_chunk(0, 0); CPCOMMIT();
        load_chunk(1, 1); CPCOMMIT();

        for (int ch = 0; ch < 8; ch++){
            const int s = ch & 1;
            CPWAIT1();
            __syncthreads();
            #pragma unroll
            for (int ks = 0; ks < 2; ks++){
                const int k = ks*16;
                uint32_t AH[2][4], AL[2][4], BH[2][4], BL[2][4];
                #pragma unroll
                for (int mi = 0; mi < 2; mi++){
                    uint32_t ad = sbase + (uint32_t)(s*10240 + ((m0 + mi*16 + l15)*40 + k + lH)*2);
                    LDSM4(AH[mi], ad);
                    LDSM4(AL[mi], ad + 5120);
                }
                #pragma unroll
                for (int bt = 0; bt < 2; bt++){
                    uint32_t bd = sbase + SB_B + (uint32_t)(s*17408 + ((k + l15)*136 + n0 + bt*16 + lH)*2);
                    LDSM4T(BH[bt], bd);
                    LDSM4T(BL[bt], bd + 8704);
                }
                #pragma unroll
                for (int mi = 0; mi < 2; mi++){
                    #pragma unroll
                    for (int nj = 0; nj < 4; nj++){
                        const int t = nj >> 1, o = (nj & 1)*2;
                        MMA(d[mi][nj], AH[mi], BH[t][o], BH[t][o+1]);
                        MMA(d[mi][nj], AL[mi], BH[t][o], BH[t][o+1]);
                        MMA(d[mi][nj], AH[mi], BL[t][o], BL[t][o+1]);
                    }
                }
            }
            __syncthreads();
            if (ch + 2 < 8) load_chunk(ch + 2, s);
            CPCOMMIT();
        }
        CPWAIT0();
        __syncthreads();

        float* sbuf = (float*)smem;
        #pragma unroll
        for (int h2 = 0; h2 < 2; h2++){
            __syncthreads();
            if (wm == h2){
                #pragma unroll
                for (int mi = 0; mi < 2; mi++){
                    int r0 = mi*16 + (lane>>2);
                    #pragma unroll
                    for (int nj = 0; nj < 4; nj++){
                        int c = n0 + nj*8 + ((lane&3)<<1);
                        sbuf[r0*132 + c]       = d[mi][nj][0];
                        sbuf[r0*132 + c + 1]   = d[mi][nj][1];
                        sbuf[(r0+8)*132 + c]   = d[mi][nj][2];
                        sbuf[(r0+8)*132 + c+1] = d[mi][nj][3];
                    }
                }
            }
            __syncthreads();
            for (int q = tid; q < 1024; q += 256){
                int r = q >> 5, cc = q & 31;
                float4 g  = *(float4*)&sbuf[r*132 + cc*4];
                float4 bv = *(const float4*)&g_b4[nb*128 + cc*4];
                size_t o = (size_t)(p0 + h2*32 + r)*128 + nb*32 + cc;
                float a  = sigmoidf_(g.x + bv.x);
                float ga = sigmoidf_(g.y + bv.y);
                float gv = tanhf   (g.z + bv.z);
                float a1 = sigmoidf_(g.w + bv.w);
                float cs = g_C[o]*a + ga*gv;
                g_C[o] = cs;
                store_hl1(g_HBh, g_HBl, o, a1 * tanhf(cs));
            }
        }
    } else {
        const int j5 = 3 + (yb - 4);
        const __half* wbH = g_W5h + (size_t)j5*128*128;
        const __half* wbL = g_W5l + (size_t)j5*128*128;

        auto load_chunk = [&](int ch, int s){
            const int k0 = ch*32;
            #pragma unroll
            for (int q = tid; q < 512; q += 256){
                int h = q >> 8, e = q & 255, r = e >> 2, seg = e & 3;
                uint32_t dst = sbase + (uint32_t)((s*2 + h)*5120 + r*80 + seg*16);
                CPA(dst, (h ? g_ml : g_mh) + (size_t)(p0 + r)*128 + k0 + seg*8);
            }
            #pragma unroll
            for (int q = tid; q < 1024; q += 256){
                int h = q >> 9, e = q & 511, r = e >> 4, seg = e & 15;
                uint32_t dst = sbase + SB_B + (uint32_t)((s*2 + h)*8704 + r*272 + seg*16);
                CPA(dst, (h ? wbL : wbH) + (size_t)(k0 + r)*128 + seg*8);
            }
        };

        float d[2][4][4];
        #pragma unroll
        for (int a=0;a<2;a++){
            #pragma unroll
            for (int b=0;b<4;b++){
                #pragma unroll
                for (int e=0;e<4;e++) d[a][b][e]=0.f; } }

        load_chunk(0, 0); CPCOMMIT();
        load_chunk(1, 1); CPCOMMIT();

        for (int ch = 0; ch < 4; ch++){
            const int s = ch & 1;
            CPWAIT1();
            __syncthreads();
            #pragma unroll
            for (int ks = 0; ks < 2; ks++){
                const int k = ks*16;
                uint32_t AH[2][4], AL[2][4], BH[2][4], BL[2][4];
                #pragma unroll
                for (int mi = 0; mi < 2; mi++){
                    uint32_t ad = sbase + (uint32_t)(s*10240 + ((m0 + mi*16 + l15)*40 + k + lH)*2);
                    LDSM4(AH[mi], ad);
                    LDSM4(AL[mi], ad + 5120);
                }
                #pragma unroll
                for (int bt = 0; bt < 2; bt++){
                    uint32_t bd = sbase + SB_B + (uint32_t)(s*17408 + ((k + l15)*136 + n0 + bt*16 + lH)*2);
                    LDSM4T(BH[bt], bd);
                    LDSM4T(BL[bt], bd + 8704);
                }
                #pragma unroll
                for (int mi = 0; mi < 2; mi++){
                    #pragma unroll
                    for (int nj = 0; nj < 4; nj++){
                        const int t = nj >> 1, o = (nj & 1)*2;
                        MMA(d[mi][nj], AH[mi], BH[t][o], BH[t][o+1]);
                        MMA(d[mi][nj], AL[mi], BH[t][o], BH[t][o+1]);
                        MMA(d[mi][nj], AH[mi], BL[t][o], BL[t][o+1]);
                    }
                }
            }
            __syncthreads();
            if (ch + 2 < 4) load_chunk(ch + 2, s);
            CPCOMMIT();
        }
        CPWAIT0();
        __syncthreads();

        float* sbuf = (float*)smem;
        #pragma unroll
        for (int h2 = 0; h2 < 2; h2++){
            __syncthreads();
            if (wm == h2){
                #pragma unroll
                for (int mi = 0; mi < 2; mi++){
                    int r0 = mi*16 + (lane>>2);
                    #pragma unroll
                    for (int nj = 0; nj < 4; nj++){
                        int c = n0 + nj*8 + ((lane&3)<<1);
                        sbuf[r0*132 + c]       = d[mi][nj][0];
                        sbuf[r0*132 + c + 1]   = d[mi][nj][1];
                        sbuf[(r0+8)*132 + c]   = d[mi][nj][2];
                        sbuf[(r0+8)*132 + c+1] = d[mi][nj][3];
                    }
                }
            }
            __syncthreads();
            for (int q = tid; q < 1024; q += 256){
                int r = q >> 5, c4 = (q & 31) << 2;
                float4 v = *(float4*)&sbuf[r*132 + c4];
                float4 bv = *(const float4*)&b5[j5*128 + c4];
                v.x += bv.x; v.y += bv.y; v.z += bv.z; v.w += bv.w;
                *(float4*)(g_Y + (size_t)(p0 + h2*32 + r)*640 + 384 + (j5-3)*128 + c4) = v;
            }
        }
    }
}

// ---------------------------------------------------------------------------
// attn_big: softmax + conv6 + conv7..9 + final gates, all for 32 pixel rows.
// smem map (bytes):
//   0      vh/zh plane [32][132]f, later A2h [32][264]h ([H_B | z] hi)
//   16896  kh plane,  later A1h [32][264]h ([zh|zm] hi)
//   33792  qt plane,  later A1l
//   50688  km plane,  later B ring [2 stages][hi/lo][32][136]h (34816 B)
//   67584  vm/zm plane (consumed by A1 build before B ring reaches it)
//   85504  A2l [32][264]h
//   total 102400
// ---------------------------------------------------------------------------
#define AT_P 132
#define A1H_OFF 16896
#define A1L_OFF 33792
#define BT_RING 50688
#define A2H_OFF 0
#define A2L_OFF 85504
#define SMEM_AB 102400
__global__ __launch_bounds__(256, 2) void attn_big(const float* __restrict__ b8){
    extern __shared__ char smemc[];
    float* s = (float*)smemc;
    const uint32_t sbase = smem_u32(smemc);
    float* s_vh = s;
    float* s_kh = s + 1*32*AT_P;
    float* s_qt = s + 2*32*AT_P;
    float* s_km = s + 3*32*AT_P;
    float* s_vm = s + 4*32*AT_P;
    const int tid = threadIdx.x;
    const int b = blockIdx.x >> 5, h = blockIdx.x & 31;
    const int r0 = b*1024 + h*32;

    // ---- phase 1: stage planes + transposed q
    for (int q = tid; q < 32*32; q += 256){
        int w = q >> 5, c4 = (q & 31) * 4;
        const float* row = g_Y + (size_t)(r0 + w)*640;
        float4 v;
        v = *(const float4*)(row +   0 + c4); *(float4*)&s_vh[w*AT_P+c4] = v;
        v = *(const float4*)(row + 128 + c4); *(float4*)&s_kh[w*AT_P+c4] = v;
        v = *(const float4*)(row + 384 + c4); *(float4*)&s_km[w*AT_P+c4] = v;
        v = *(const float4*)(row + 512 + c4); *(float4*)&s_vm[w*AT_P+c4] = v;
        const float* qrow = g_Y + (size_t)(b*1024 + w*32 + h)*640 + 256;
        v = *(const float4*)(qrow + c4);      *(float4*)&s_qt[w*AT_P+c4] = v;
    }
    __syncthreads();

    // ---- phase 2: softmaxes (zh -> s_vh, zm -> s_vm)
    {
        const int wid = tid >> 5, lane = tid & 31;
        for (int i = 0; i < 16; i++){
            int c = wid + 8*i;
            float qv = s_qt[lane*AT_P + c];
            float s1 = s_kh[lane*AT_P + c] * qv;
            float mx = s1;
            #pragma unroll
            for (int o = 16; o; o >>= 1) mx = fmaxf(mx, __shfl_xor_sync(0xffffffffu, mx, o));
            float e1 = expf(s1 - mx), sm = e1;
            #pragma unroll
            for (int o = 16; o; o >>= 1) sm += __shfl_xor_sync(0xffffffffu, sm, o);
            s_vh[lane*AT_P + c] *= (e1 / sm);
            float s2 = qv * s_km[lane*AT_P + c];
            float mx2 = s2;
            #pragma unroll
            for (int o = 16; o; o >>= 1) mx2 = fmaxf(mx2, __shfl_xor_sync(0xffffffffu, mx2, o));
            float e2 = expf(s2 - mx2), sm2 = e2;
            #pragma unroll
            for (int o = 16; o; o >>= 1) sm2 += __shfl_xor_sync(0xffffffffu, sm2, o);
            s_vm[lane*AT_P + c] *= (e2 / sm2);
        }
    }
    __syncthreads();

    // ---- phase 3: build A1 = [zh | zm] hi/lo, stride 264 halfs
    {
        __half* Ah = (__half*)(smemc + A1H_OFF);
        __half* Al = (__half*)(smemc + A1L_OFF);
        for (int q = tid; q < 32*64; q += 256){
            int r = q >> 6, c4 = (q & 63) * 4;
            float4 v = (c4 < 128) ? *(float4*)&s_vh[r*AT_P + c4]
                                  : *(float4*)&s_vm[r*AT_P + (c4 - 128)];
            __half2 h01 = __floats2half2_rn(v.x, v.y);
            __half2 h23 = __floats2half2_rn(v.z, v.w);
            __half2 l01 = __floats2half2_rn(v.x - __low2float(h01), v.y - __high2float(h01));
            __half2 l23 = __floats2half2_rn(v.z - __low2float(h23), v.w - __high2float(h23));
            int o = r*264 + c4;
            *(__half2*)(Ah + o) = h01; *(__half2*)(Ah + o + 2) = h23;
            *(__half2*)(Al + o) = l01; *(__half2*)(Al + o + 2) = l23;
        }
    }
    __syncthreads();

    // ---- phase 3b: stage H_B into A2 cols 0..127 (A2h overwrites dead zh plane)
    {
        __half* A2h = (__half*)(smemc + A2H_OFF);
        __half* A2l = (__half*)(smemc + A2L_OFF);
        for (int q = tid; q < 1024; q += 256){
            int hl = q >> 9, e = q & 511, r = e >> 4, seg = e & 15;
            const __half* src = (hl ? g_HBl : g_HBh) + (size_t)(r0 + r)*128 + seg*8;
            uint4 v = *(const uint4*)src;
            *(uint4*)((hl ? A2l : A2h) + r*264 + seg*8) = v;
        }
    }

    // ---- phase 4: four sub-GEMMs (conv6, conv7, conv8, conv9), M=32 N=128 K=256
    const int wid = tid >> 5, lane = tid & 31;
    const int wm = wid >> 2, wn = wid & 3;
    const int m0 = wm*16, n0 = wn*32;
    const int l15 = lane & 15, lH = (lane >> 4) << 3;
    const int rA = m0 + (lane >> 2), rB = rA + 8;   // frag row mapping

    float dOT[4][2][2], dGT[4][2][2];               // [nj][rowhalf][colpair]

    for (int jj = 0; jj < 4; jj++){
        const int j = jj;                            // conv6=W8[0], conv7..9=W8[1..3]
        const __half* WjH = g_W8h + (size_t)j*256*128;
        const __half* WjL = g_W8l + (size_t)j*256*128;
        const uint32_t aBase = sbase + ((jj == 0) ? A1H_OFF : A2H_OFF);
        const uint32_t aLoD  = (jj == 0) ? (uint32_t)(A1L_OFF - A1H_OFF)
                                         : (uint32_t)(A2L_OFF - A2H_OFF);

        auto load_b = [&](int ch, int st){
            const int k0 = ch*32;
            #pragma unroll
            for (int q = tid; q < 1024; q += 256){
                int hh = q >> 9, e = q & 511, r = e >> 4, seg = e & 15;
                uint32_t dst = sbase + BT_RING + (uint32_t)(st*17408 + hh*8704 + r*272 + seg*16);
                CPA(dst, (hh ? WjL : WjH) + (size_t)(k0 + r)*128 + seg*8);
            }
        };

        float d[4][4];
        #pragma unroll
        for (int a=0;a<4;a++){
            #pragma unroll
            for (int e=0;e<4;e++) d[a][e]=0.f; }

        load_b(0, 0); CPCOMMIT();
        load_b(1, 1); CPCOMMIT();

        for (int ch = 0; ch < 8; ch++){
            const int st = ch & 1;
            CPWAIT1();
            __syncthreads();
            #pragma unroll
            for (int ks = 0; ks < 2; ks++){
                const int kk = ch*32 + ks*16;
                uint32_t AH[4], AL[4], BH[2][4], BL[2][4];
                uint32_t ad = aBase + (uint32_t)(((m0 + l15)*264 + kk + lH)*2);
                LDSM4(AH, ad);
                LDSM4(AL, ad + aLoD);
                #pragma unroll
                for (int bt = 0; bt < 2; bt++){
                    uint32_t bd = sbase + BT_RING + (uint32_t)(st*17408 + ((ks*16 + l15)*136 + n0 + bt*16 + lH)*2);
                    LDSM4T(BH[bt], bd);
                    LDSM4T(BL[bt], bd + 8704);
                }
                #pragma unroll
                for (int nj = 0; nj < 4; nj++){
                    const int t = nj >> 1, o = (nj & 1)*2;
                    MMA(d[nj], AH, BH[t][o], BH[t][o+1]);
                    MMA(d[nj], AL, BH[t][o], BH[t][o+1]);
                    MMA(d[nj], AH, BL[t][o], BL[t][o+1]);
                }
            }
            __syncthreads();
            if (ch + 2 < 8) load_b(ch + 2, st);
            CPCOMMIT();
        }
        CPWAIT0();

        // ---- per-conv epilogue (frag-private, no cross-warp exchange)
        if (jj == 0){
            // z = d + b8[0][c] -> A2 cols 128..255 (hi/lo)
            __half* A2h = (__half*)(smemc + A2H_OFF);
            __half* A2l = (__half*)(smemc + A2L_OFF);
            #pragma unroll
            for (int nj = 0; nj < 4; nj++){
                int c = n0 + nj*8 + ((lane&3)<<1);
                float z0 = d[nj][0] + b8[c];
                float z1 = d[nj][1] + b8[c+1];
                float z2 = d[nj][2] + b8[c];
                float z3 = d[nj][3] + b8[c+1];
                store_hl1(A2h, A2l, (size_t)rA*264 + 128 + c,     z0);
                store_hl1(A2h, A2l, (size_t)rA*264 + 128 + c + 1, z1);
                store_hl1(A2h, A2l, (size_t)rB*264 + 128 + c,     z2);
                store_hl1(A2h, A2l, (size_t)rB*264 + 128 + c + 1, z3);
            }
            __syncthreads();
        } else if (jj == 1){
            #pragma unroll
            for (int nj = 0; nj < 4; nj++){
                int c = n0 + nj*8 + ((lane&3)<<1);
                dOT[nj][0][0] = d[nj][0] + b8[128 + c];
                dOT[nj][0][1] = d[nj][1] + b8[128 + c + 1];
                dOT[nj][1][0] = d[nj][2] + b8[128 + c];
                dOT[nj][1][1] = d[nj][3] + b8[128 + c + 1];
            }
        } else if (jj == 2){
            #pragma unroll
            for (int nj = 0; nj < 4; nj++){
                int c = n0 + nj*8 + ((lane&3)<<1);
                dGT[nj][0][0] = d[nj][0] + b8[256 + c];
                dGT[nj][0][1] = d[nj][1] + b8[256 + c + 1];
                dGT[nj][1][0] = d[nj][2] + b8[256 + c];
                dGT[nj][1][1] = d[nj][3] + b8[256 + c + 1];
            }
        } else {
            #pragma unroll
            for (int nj = 0; nj < 4; nj++){
                int c = n0 + nj*8 + ((lane&3)<<1);
                #pragma unroll
                for (int rh = 0; rh < 2; rh++){
                    int rr = (rh ? rB : rA);
                    #pragma unroll
                    for (int cp = 0; cp < 2; cp++){
                        float itv = sigmoidf_(d[nj][rh*2 + cp] + b8[384 + c + cp]);
                        size_t o = (size_t)(r0 + rr)*128 + c + cp;
                        float mt = tanhf(dGT[nj][rh][cp])*itv + (1.f - itv)*g_m[o];
                        g_m[o] = mt;
                        store_hl1(g_mh, g_ml, o, mt);
                        float hv = sigmoidf_(dOT[nj][rh][cp])*mt;
                        g_H32[o] = hv;
                        store_hl1(g_HAh, g_HAl, o, hv);
                    }
                }
            }
        }
    }
}

// ---------------- layout transposes ----------------------------------------
#define SMEM_TR (128*132*4)
__global__ __launch_bounds__(256) void k_xT(const float* __restrict__ x){
    extern __shared__ float s[];
    int bid = blockIdx.x;
    int b = bid >> 7, t = (bid >> 3) & 15, n0 = (bid & 7) * 128;
    const float* src = x + (size_t)(b*16 + t)*128*1024;
    for (int q = threadIdx.x; q < 128*32; q += 256){
        int c = q >> 5, n4 = (q & 31) * 4;
        float4 v = *(const float4*)(src + (size_t)c*1024 + n0 + n4);
        s[(n4+0)*132 + c] = v.x; s[(n4+1)*132 + c] = v.y;
        s[(n4+2)*132 + c] = v.z; s[(n4+3)*132 + c] = v.w;
    }
    __syncthreads();
    size_t base = ((size_t)t*NPIX + b*1024 + n0)*128;
    for (int q = threadIdx.x; q < 128*32; q += 256){
        int n = q >> 5, c4 = (q & 31) * 4;
        store_hl(g_xTh, g_xTl, base + (size_t)n*128 + c4, *(float4*)&s[n*132 + c4]);
    }
}
__global__ __launch_bounds__(256) void k_init(const float* __restrict__ c0){
    extern __shared__ float s[];
    int b = blockIdx.x >> 3, n0 = (blockIdx.x & 7) * 128;
    const float* src = c0 + (size_t)b*128*1024;
    for (int q = threadIdx.x; q < 128*32; q += 256){
        int c = q >> 5, n4 = (q & 31) * 4;
        float4 v = *(const float4*)(src + (size_t)c*1024 + n0 + n4);
        s[(n4+0)*132 + c] = v.x; s[(n4+1)*132 + c] = v.y;
        s[(n4+2)*132 + c] = v.z; s[(n4+3)*132 + c] = v.w;
    }
    __syncthreads();
    size_t base = (size_t)(b*1024 + n0)*128;
    float4 zz = {0.f,0.f,0.f,0.f};
    for (int q = threadIdx.x; q < 128*32; q += 256){
        int n = q >> 5, c4 = (q & 31) * 4;
        size_t o = base + (size_t)n*128 + c4;
        *(float4*)(g_C + o) = *(float4*)&s[n*132 + c4];
        *(float4*)(g_m + o) = zz;
        store_hl(g_HAh, g_HAl, o, zz);
        store_hl(g_mh, g_ml, o, zz);
    }
}
__global__ __launch_bounds__(256) void k_outT(float* __restrict__ out){
    extern __shared__ float s[];
    int b = blockIdx.x >> 3, n0 = (blockIdx.x & 7) * 128;
    const float* src = g_H32 + (size_t)(b*1024 + n0)*128;
    for (int q = threadIdx.x; q < 128*32; q += 256){
        int n = q >> 5, c4 = (q & 31) * 4;
        float4 v = *(const float4*)(src + (size_t)n*128 + c4);
        s[(c4+0)*132 + n] = v.x; s[(c4+1)*132 + n] = v.y;
        s[(c4+2)*132 + n] = v.z; s[(c4+3)*132 + n] = v.w;
    }
    __syncthreads();
    float* dst = out + (size_t)b*128*1024;
    for (int q = threadIdx.x; q < 128*32; q += 256){
        int c = q >> 5, n4 = (q & 31) * 4;
        *(float4*)(dst + (size_t)c*1024 + n0 + n4) = *(float4*)&s[c*132 + n4];
    }
}

// ---------------------------------------------------------------------------
extern "C" void kernel_launch(void* const* d_in, const int* in_sizes, int n_in,
                              void* d_out, int out_size)
{
    const float* x  = (const float*)d_in[0];
    const float* c0 = (const float*)d_in[1];
    const float* W5 = (const float*)d_in[2];
    const float* b5 = (const float*)d_in[3];
    const float* W8 = (const float*)d_in[4];
    const float* b8 = (const float*)d_in[5];
    float* out = (float*)d_out;

    cudaFuncSetAttribute(gemm2,      cudaFuncAttributeMaxDynamicSharedMemorySize, SMEM_G2);
    cudaFuncSetAttribute(gemm_step1, cudaFuncAttributeMaxDynamicSharedMemorySize, SMEM_G2);
    cudaFuncSetAttribute(attn_big, cudaFuncAttributeMaxDynamicSharedMemorySize, SMEM_AB);
    cudaFuncSetAttribute(k_xT,   cudaFuncAttributeMaxDynamicSharedMemorySize, SMEM_TR);
    cudaFuncSetAttribute(k_init, cudaFuncAttributeMaxDynamicSharedMemorySize, SMEM_TR);
    cudaFuncSetAttribute(k_outT, cudaFuncAttributeMaxDynamicSharedMemorySize, SMEM_TR);

    float *pY;
    __half *pHBh,*pHBl,*pxTh,*pxTl,*pW5h,*pW5l;
    cudaGetSymbolAddress((void**)&pY,  g_Y);
    cudaGetSymbolAddress((void**)&pHBh,g_HBh); cudaGetSymbolAddress((void**)&pHBl,g_HBl);
    cudaGetSymbolAddress((void**)&pxTh,g_xTh); cudaGetSymbolAddress((void**)&pxTl,g_xTl);
    cudaGetSymbolAddress((void**)&pW5h,g_W5h); cudaGetSymbolAddress((void**)&pW5l,g_W5l);

    k_wprep<<<1860, 256>>>(W5, W8, b8);
    k_xT<<<2048, 256, SMEM_TR>>>(x);
    k_init<<<128, 256, SMEM_TR>>>(c0);

    for (int t = 0; t < TT; t++){
        const size_t xo = (size_t)t*NPIX*128;
        // conv10..13 + LSTM gates (H_A -> H_B, C update) || conv4..5 on m -> Y[384:640]
        gemm_step1<<<dim3(256,6), 256, SMEM_G2>>>(pxTh + xo, pxTl + xo, b5);
        // conv1..3 on H_B -> Y[0:384]
        gemm2<<<dim3(256,3), 256, SMEM_G2>>>(pHBh, pHBl, pHBh, pHBl, 128,
            128, pW5h, pW5l, b5, pY, 640, 0);
        // attention + conv6 + conv7..9 + final gates (m update, H -> H_A, H32)
        attn_big<<<512, 256, SMEM_AB>>>(b8);
    }
    k_outT<<<128, 256, SMEM_TR>>>(out);
}

// round 13
// speedup vs baseline: 1.1150x; 1.1150x over previous
#include <cuda_runtime.h>
#include <cuda_fp16.h>
#include <math.h>
#include <stdint.h>

#define NPIX 16384
#define TT 16

// ---------------- device scratch -------------------------------------------
__device__ float g_C  [NPIX*128];
__device__ float g_m  [NPIX*128];
__device__ float g_H32[NPIX*128];
__device__ float g_Y  [NPIX*640];               // vh|kh|qh|km|vm (fp32)
__device__ float g_g3 [NPIX*384];               // conv7..9 raw
__device__ __half g_HAh[NPIX*128], g_HAl[NPIX*128];   // H ping
__device__ __half g_HBh[NPIX*128], g_HBl[NPIX*128];   // H pong
__device__ __half g_mh[NPIX*128],  g_ml[NPIX*128];
__device__ __half g_zfh[NPIX*128], g_zfl[NPIX*128];   // z (conv6 out)
__device__ __half g_xTh[(size_t)TT*NPIX*128], g_xTl[(size_t)TT*NPIX*128];
__device__ __half g_W5h[5*128*128], g_W5l[5*128*128];     // [j][k][o]
__device__ __half g_W8h[8*256*128], g_W8l[8*256*128];     // [j][k][o]
__device__ __half g_W4h[256*512], g_W4l[256*512];         // conv10..13 interleaved
__device__ float g_b4[512];

__device__ __forceinline__ float sigmoidf_(float x){ return 1.f/(1.f+expf(-x)); }
__device__ __forceinline__ uint32_t smem_u32(const void* p){
    uint32_t a; asm("{ .reg .u64 t; cvta.to.shared.u64 t, %1; cvt.u32.u64 %0, t; }":"=r"(a):"l"(p)); return a;
}
__device__ __forceinline__ void store_hl(__half* Ph, __half* Pl, size_t off, float4 v){
    __half2 h01 = __floats2half2_rn(v.x, v.y);
    __half2 h23 = __floats2half2_rn(v.z, v.w);
    __half2 l01 = __floats2half2_rn(v.x - __low2float(h01), v.y - __high2float(h01));
    __half2 l23 = __floats2half2_rn(v.z - __low2float(h23), v.w - __high2float(h23));
    *(__half2*)(Ph+off) = h01; *(__half2*)(Ph+off+2) = h23;
    *(__half2*)(Pl+off) = l01; *(__half2*)(Pl+off+2) = l23;
}
__device__ __forceinline__ void store_hl1(__half* Ph, __half* Pl, size_t off, float v){
    __half h = __float2half_rn(v);
    Ph[off] = h;
    Pl[off] = __float2half_rn(v - __half2float(h));
}

#define LDSM4(r, a) asm volatile("ldmatrix.sync.aligned.m8n8.x4.shared.b16 {%0,%1,%2,%3}, [%4];" \
  : "=r"((r)[0]),"=r"((r)[1]),"=r"((r)[2]),"=r"((r)[3]) : "r"(a))
#define LDSM4T(r, a) asm volatile("ldmatrix.sync.aligned.m8n8.x4.trans.shared.b16 {%0,%1,%2,%3}, [%4];" \
  : "=r"((r)[0]),"=r"((r)[1]),"=r"((r)[2]),"=r"((r)[3]) : "r"(a))
#define MMA(d, a, b0_, b1_) asm volatile( \
  "mma.sync.aligned.m16n8k16.row.col.f32.f16.f16.f32 {%0,%1,%2,%3},{%4,%5,%6,%7},{%8,%9},{%0,%1,%2,%3};" \
  : "+f"((d)[0]),"+f"((d)[1]),"+f"((d)[2]),"+f"((d)[3]) \
  : "r"((a)[0]),"r"((a)[1]),"r"((a)[2]),"r"((a)[3]), "r"(b0_),"r"(b1_))
#define MMA1(d, a0_, a1_, a2_, a3_, b0_, b1_) asm volatile( \
  "mma.sync.aligned.m16n8k16.row.col.f32.f16.f16.f32 {%0,%1,%2,%3},{%4,%5,%6,%7},{%8,%9},{%0,%1,%2,%3};" \
  : "+f"((d)[0]),"+f"((d)[1]),"+f"((d)[2]),"+f"((d)[3]) \
  : "r"(a0_),"r"(a1_),"r"(a2_),"r"(a3_), "r"(b0_),"r"(b1_))
#define CPA(dst, src) asm volatile("cp.async.cg.shared.global [%0], [%1], 16;"::"r"(dst),"l"(src))
#define CPCOMMIT()    asm volatile("cp.async.commit_group;")
#define CPWAIT1()     asm volatile("cp.async.wait_group 1;")
#define CPWAIT0()     asm volatile("cp.async.wait_group 0;")

#define SB_B     20480
#define SMEM_G2  55296

// ---------------- weight prep ----------------------------------------------
__global__ void k_wprep(const float* __restrict__ W5, const float* __restrict__ W8,
                        const float* __restrict__ b8){
    int idx = blockIdx.x*blockDim.x + threadIdx.x;
    if (idx < 81920){
        int j = idx/16384, r = idx%16384, o = r/128, k = r%128;
        float v = W5[idx];
        __half h = __float2half_rn(v);
        g_W5h[(j*128 + k)*128 + o] = h;
        g_W5l[(j*128 + k)*128 + o] = __float2half_rn(v - __half2float(h));
        return;
    }
    int i2 = idx - 81920;
    if (i2 < 262144){
        int j = i2/32768, r = i2%32768, o = r/256, k = r%256;
        float v = W8[i2];
        __half h = __float2half_rn(v);
        g_W8h[((size_t)j*256 + k)*128 + o] = h;
        g_W8l[((size_t)j*256 + k)*128 + o] = __float2half_rn(v - __half2float(h));
        return;
    }
    int i3 = i2 - 262144;
    if (i3 < 131072){
        int k = i3 >> 9, n = i3 & 511;
        int jj = n & 3, c = n >> 2;
        float v = W8[(size_t)(4+jj)*32768 + c*256 + k];
        __half h = __float2half_rn(v);
        g_W4h[k*512 + n] = h;
        g_W4l[k*512 + n] = __float2half_rn(v - __half2float(h));
        return;
    }
    int i5 = i3 - 131072;
    if (i5 < 512){ g_b4[i5] = b8[(4 + (i5 & 3))*128 + (i5 >> 2)]; }
}

// ---------------------------------------------------------------------------
// gemm2: generic conv GEMM. 64-pixel x 128-out CTA tile, warp tile 32x32.
// ---------------------------------------------------------------------------
__global__ __launch_bounds__(256, 3)
void gemm2(const __half* __restrict__ A0h, const __half* __restrict__ A0l,
           const __half* __restrict__ A1h, const __half* __restrict__ A1l, int S,
           int K, const __half* __restrict__ Wh, const __half* __restrict__ Wl,
           const float* __restrict__ bias,
           float* __restrict__ outF, int outStride, int outColOff)
{
    extern __shared__ char smem[];
    const uint32_t sbase = smem_u32(smem);
    const int tid = threadIdx.x, wid = tid >> 5, lane = tid & 31;
    const int p0 = blockIdx.x * 64;
    const int j  = blockIdx.y;

    const int wm = wid >> 2, wn = wid & 3;
    const int m0 = wm*32, n0 = wn*32;
    const int l15 = lane & 15, lH = (lane >> 4) << 3;

    const __half* wbH = Wh + (size_t)j*K*128;
    const __half* wbL = Wl + (size_t)j*K*128;

    auto load_chunk = [&](int ch, int s){
        const int k0 = ch*32;
        const __half *srcH, *srcL; int koff;
        if (k0 < S){ srcH = A0h; srcL = A0l; koff = k0; }
        else       { srcH = A1h; srcL = A1l; koff = k0 - S; }
        #pragma unroll
        for (int q = tid; q < 512; q += 256){
            int h = q >> 8, e = q & 255, r = e >> 2, seg = e & 3;
            uint32_t dst = sbase + (uint32_t)((s*2 + h)*5120 + r*80 + seg*16);
            CPA(dst, (h ? srcL : srcH) + (size_t)(p0 + r)*128 + koff + seg*8);
        }
        #pragma unroll
        for (int q = tid; q < 1024; q += 256){
            int h = q >> 9, e = q & 511, r = e >> 4, seg = e & 15;
            uint32_t dst = sbase + SB_B + (uint32_t)((s*2 + h)*8704 + r*272 + seg*16);
            CPA(dst, (h ? wbL : wbH) + (size_t)(k0 + r)*128 + seg*8);
        }
    };

    float d[2][4][4];
    #pragma unroll
    for (int a=0;a<2;a++){
        #pragma unroll
        for (int b=0;b<4;b++){
            #pragma unroll
            for (int e=0;e<4;e++) d[a][b][e]=0.f; } }

    const int CH = K >> 5;
    load_chunk(0, 0); CPCOMMIT();
    if (CH > 1) load_chunk(1, 1);
    CPCOMMIT();

    for (int ch = 0; ch < CH; ch++){
        const int s = ch & 1;
        CPWAIT1();
        __syncthreads();
        #pragma unroll
        for (int ks = 0; ks < 2; ks++){
            const int k = ks*16;
            uint32_t AH[2][4], AL[2][4], BH[2][4], BL[2][4];
            #pragma unroll
            for (int mi = 0; mi < 2; mi++){
                uint32_t ad = sbase + (uint32_t)(s*10240 + ((m0 + mi*16 + l15)*40 + k + lH)*2);
                LDSM4(AH[mi], ad);
                LDSM4(AL[mi], ad + 5120);
            }
            #pragma unroll
            for (int bt = 0; bt < 2; bt++){
                uint32_t bd = sbase + SB_B + (uint32_t)(s*17408 + ((k + l15)*136 + n0 + bt*16 + lH)*2);
                LDSM4T(BH[bt], bd);
                LDSM4T(BL[bt], bd + 8704);
            }
            #pragma unroll
            for (int mi = 0; mi < 2; mi++){
                #pragma unroll
                for (int nj = 0; nj < 4; nj++){
                    const int t = nj >> 1, o = (nj & 1)*2;
                    MMA(d[mi][nj], AH[mi], BH[t][o], BH[t][o+1]);
                    MMA(d[mi][nj], AL[mi], BH[t][o], BH[t][o+1]);
                    MMA(d[mi][nj], AH[mi], BL[t][o], BL[t][o+1]);
                }
            }
        }
        __syncthreads();
        if (ch + 2 < CH) load_chunk(ch + 2, s);
        CPCOMMIT();
    }
    CPWAIT0();
    __syncthreads();

    float* sbuf = (float*)smem;
    #pragma unroll
    for (int h2 = 0; h2 < 2; h2++){
        __syncthreads();
        if (wm == h2){
            #pragma unroll
            for (int mi = 0; mi < 2; mi++){
                int r0 = mi*16 + (lane>>2);
                #pragma unroll
                for (int nj = 0; nj < 4; nj++){
                    int c = n0 + nj*8 + ((lane&3)<<1);
                    sbuf[r0*132 + c]       = d[mi][nj][0];
                    sbuf[r0*132 + c + 1]   = d[mi][nj][1];
                    sbuf[(r0+8)*132 + c]   = d[mi][nj][2];
                    sbuf[(r0+8)*132 + c+1] = d[mi][nj][3];
                }
            }
        }
        __syncthreads();
        for (int q = tid; q < 32*32; q += 256){
            int r = q >> 5, c4 = (q & 31) << 2;
            float4 v = *(float4*)&sbuf[r*132 + c4];
            float4 bv = *(const float4*)&bias[j*128 + c4];
            v.x += bv.x; v.y += bv.y; v.z += bv.z; v.w += bv.w;
            *(float4*)(outF + (size_t)(p0 + h2*32 + r)*outStride + outColOff + j*128 + c4) = v;
        }
    }
}

// ---------------------------------------------------------------------------
// gemm_step1: y<4 -> conv10..13 interleaved + fused LSTM gates (H_A->H_B, C);
//             y in {4,5} -> conv4..5 on m -> g_Y[384 + (y-4)*128].
// ---------------------------------------------------------------------------
__global__ __launch_bounds__(256, 3)
void gemm_step1(const __half* __restrict__ Xh, const __half* __restrict__ Xl,
                const float* __restrict__ b5)
{
    extern __shared__ char smem[];
    const uint32_t sbase = smem_u32(smem);
    const int tid = threadIdx.x, wid = tid >> 5, lane = tid & 31;
    const int p0 = blockIdx.x * 64;
    const int yb = blockIdx.y;

    const int wm = wid >> 2, wn = wid & 3;
    const int m0 = wm*32, n0 = wn*32;
    const int l15 = lane & 15, lH = (lane >> 4) << 3;

    if (yb < 4){
        const int nb = yb;
        auto load_chunk = [&](int ch, int s){
            const int k0 = ch*32;
            const __half *srcH, *srcL; int koff;
            if (k0 < 128){ srcH = g_HAh; srcL = g_HAl; koff = k0; }
            else         { srcH = Xh;    srcL = Xl;    koff = k0 - 128; }
            #pragma unroll
            for (int q = tid; q < 512; q += 256){
                int h = q >> 8, e = q & 255, r = e >> 2, seg = e & 3;
                uint32_t dst = sbase + (uint32_t)((s*2 + h)*5120 + r*80 + seg*16);
                CPA(dst, (h ? srcL : srcH) + (size_t)(p0 + r)*128 + koff + seg*8);
            }
            #pragma unroll
            for (int q = tid; q < 1024; q += 256){
                int h = q >> 9, e = q & 511, r = e >> 4, seg = e & 15;
                uint32_t dst = sbase + SB_B + (uint32_t)((s*2 + h)*8704 + r*272 + seg*16);
                CPA(dst, (h ? g_W4l : g_W4h) + (size_t)(k0 + r)*512 + nb*128 + seg*8);
            }
        };

        float d[2][4][4];
        #pragma unroll
        for (int a=0;a<2;a++){
            #pragma unroll
            for (int b=0;b<4;b++){
                #pragma unroll
                for (int e=0;e<4;e++) d[a][b][e]=0.f; } }

        load_chunk(0, 0); CPCOMMIT();
        load_chunk(1, 1); CPCOMMIT();

        for (int ch = 0; ch < 8; ch++){
            const int s = ch & 1;
            CPWAIT1();
            __syncthreads();
            #pragma unroll
            for (int ks = 0; ks < 2; ks++){
                const int k = ks*16;
                uint32_t AH[2][4], AL[2][4], BH[2][4], BL[2][4];
                #pragma unroll
                for (int mi = 0; mi < 2; mi++){
                    uint32_t ad = sbase + (uint32_t)(s*10240 + ((m0 + mi*16 + l15)*40 + k + lH)*2);
                    LDSM4(AH[mi], ad);
                    LDSM4(AL[mi], ad + 5120);
                }
                #pragma unroll
                for (int bt = 0; bt < 2; bt++){
                    uint32_t bd = sbase + SB_B + (uint32_t)(s*17408 + ((k + l15)*136 + n0 + bt*16 + lH)*2);
                    LDSM4T(BH[bt], bd);
                    LDSM4T(BL[bt], bd + 8704);
                }
                #pragma unroll
                for (int mi = 0; mi < 2; mi++){
                    #pragma unroll
                    for (int nj = 0; nj < 4; nj++){
                        const int t = nj >> 1, o = (nj & 1)*2;
                        MMA(d[mi][nj], AH[mi], BH[t][o], BH[t][o+1]);
                        MMA(d[mi][nj], AL[mi], BH[t][o], BH[t][o+1]);
                        MMA(d[mi][nj], AH[mi], BL[t][o], BL[t][o+1]);
                    }
                }
            }
            __syncthreads();
            if (ch + 2 < 8) load_chunk(ch + 2, s);
            CPCOMMIT();
        }
        CPWAIT0();
        __syncthreads();

        float* sbuf = (float*)smem;
        #pragma unroll
        for (int h2 = 0; h2 < 2; h2++){
            __syncthreads();
            if (wm == h2){
                #pragma unroll
                for (int mi = 0; mi < 2; mi++){
                    int r0 = mi*16 + (lane>>2);
                    #pragma unroll
                    for (int nj = 0; nj < 4; nj++){
                        int c = n0 + nj*8 + ((lane&3)<<1);
                        sbuf[r0*132 + c]       = d[mi][nj][0];
                        sbuf[r0*132 + c + 1]   = d[mi][nj][1];
                        sbuf[(r0+8)*132 + c]   = d[mi][nj][2];
                        sbuf[(r0+8)*132 + c+1] = d[mi][nj][3];
                    }
                }
            }
            __syncthreads();
            for (int q = tid; q < 1024; q += 256){
                int r = q >> 5, cc = q & 31;
                float4 g  = *(float4*)&sbuf[r*132 + cc*4];
                float4 bv = *(const float4*)&g_b4[nb*128 + cc*4];
                size_t o = (size_t)(p0 + h2*32 + r)*128 + nb*32 + cc;
                float a  = sigmoidf_(g.x + bv.x);
                float ga = sigmoidf_(g.y + bv.y);
                float gv = tanhf   (g.z + bv.z);
                float a1 = sigmoidf_(g.w + bv.w);
                float cs = g_C[o]*a + ga*gv;
                g_C[o] = cs;
                store_hl1(g_HBh, g_HBl, o, a1 * tanhf(cs));
            }
        }
    } else {
        const int j5 = 3 + (yb - 4);
        const __half* wbH = g_W5h + (size_t)j5*128*128;
        const __half* wbL = g_W5l + (size_t)j5*128*128;

        auto load_chunk = [&](int ch, int s){
            const int k0 = ch*32;
            #pragma unroll
            for (int q = tid; q < 512; q += 256){
                int h = q >> 8, e = q & 255, r = e >> 2, seg = e & 3;
                uint32_t dst = sbase + (uint32_t)((s*2 + h)*5120 + r*80 + seg*16);
                CPA(dst, (h ? g_ml : g_mh) + (size_t)(p0 + r)*128 + k0 + seg*8);
            }
            #pragma unroll
            for (int q = tid; q < 1024; q += 256){
                int h = q >> 9, e = q & 511, r = e >> 4, seg = e & 15;
                uint32_t dst = sbase + SB_B + (uint32_t)((s*2 + h)*8704 + r*272 + seg*16);
                CPA(dst, (h ? wbL : wbH) + (size_t)(k0 + r)*128 + seg*8);
            }
        };

        float d[2][4][4];
        #pragma unroll
        for (int a=0;a<2;a++){
            #pragma unroll
            for (int b=0;b<4;b++){
                #pragma unroll
                for (int e=0;e<4;e++) d[a][b][e]=0.f; } }

        load_chunk(0, 0); CPCOMMIT();
        load_chunk(1, 1); CPCOMMIT();

        for (int ch = 0; ch < 4; ch++){
            const int s = ch & 1;
            CPWAIT1();
            __syncthreads();
            #pragma unroll
            for (int ks = 0; ks < 2; ks++){
                const int k = ks*16;
                uint32_t AH[2][4], AL[2][4], BH[2][4], BL[2][4];
                #pragma unroll
                for (int mi = 0; mi < 2; mi++){
                    uint32_t ad = sbase + (uint32_t)(s*10240 + ((m0 + mi*16 + l15)*40 + k + lH)*2);
                    LDSM4(AH[mi], ad);
                    LDSM4(AL[mi], ad + 5120);
                }
                #pragma unroll
                for (int bt = 0; bt < 2; bt++){
                    uint32_t bd = sbase + SB_B + (uint32_t)(s*17408 + ((k + l15)*136 + n0 + bt*16 + lH)*2);
                    LDSM4T(BH[bt], bd);
                    LDSM4T(BL[bt], bd + 8704);
                }
                #pragma unroll
                for (int mi = 0; mi < 2; mi++){
                    #pragma unroll
                    for (int nj = 0; nj < 4; nj++){
                        const int t = nj >> 1, o = (nj & 1)*2;
                        MMA(d[mi][nj], AH[mi], BH[t][o], BH[t][o+1]);
                        MMA(d[mi][nj], AL[mi], BH[t][o], BH[t][o+1]);
                        MMA(d[mi][nj], AH[mi], BL[t][o], BL[t][o+1]);
                    }
                }
            }
            __syncthreads();
            if (ch + 2 < 4) load_chunk(ch + 2, s);
            CPCOMMIT();
        }
        CPWAIT0();
        __syncthreads();

        float* sbuf = (float*)smem;
        #pragma unroll
        for (int h2 = 0; h2 < 2; h2++){
            __syncthreads();
            if (wm == h2){
                #pragma unroll
                for (int mi = 0; mi < 2; mi++){
                    int r0 = mi*16 + (lane>>2);
                    #pragma unroll
                    for (int nj = 0; nj < 4; nj++){
                        int c = n0 + nj*8 + ((lane&3)<<1);
                        sbuf[r0*132 + c]       = d[mi][nj][0];
                        sbuf[r0*132 + c + 1]   = d[mi][nj][1];
                        sbuf[(r0+8)*132 + c]   = d[mi][nj][2];
                        sbuf[(r0+8)*132 + c+1] = d[mi][nj][3];
                    }
                }
            }
            __syncthreads();
            for (int q = tid; q < 1024; q += 256){
                int r = q >> 5, c4 = (q & 31) << 2;
                float4 v = *(float4*)&sbuf[r*132 + c4];
                float4 bv = *(const float4*)&b5[j5*128 + c4];
                v.x += bv.x; v.y += bv.y; v.z += bv.z; v.w += bv.w;
                *(float4*)(g_Y + (size_t)(p0 + h2*32 + r)*640 + 384 + (j5-3)*128 + c4) = v;
            }
        }
    }
}

// ---------------------------------------------------------------------------
// attn6: attention softmax + fused conv6 GEMM -> z (fp16 hi/lo).
// ---------------------------------------------------------------------------
#define AT_P 132
#define AT_AHI  16896
#define AT_ALO  33792
#define AT_B    50688
#define SMEM_AT 85504
__global__ __launch_bounds__(256, 2) void attn6(const float* __restrict__ b8){
    extern __shared__ char smemc[];
    float* s = (float*)smemc;
    const uint32_t sbase = smem_u32(smemc);
    float* s_vh = s;
    float* s_kh = s + 1*32*AT_P;
    float* s_qt = s + 2*32*AT_P;
    float* s_km = s + 3*32*AT_P;
    float* s_vm = s + 4*32*AT_P;
    const int tid = threadIdx.x;
    const int b = blockIdx.x >> 5, h = blockIdx.x & 31;
    const int r0 = b*1024 + h*32;

    for (int q = tid; q < 32*32; q += 256){
        int w = q >> 5, c4 = (q & 31) * 4;
        const float* row = g_Y + (size_t)(r0 + w)*640;
        float4 v;
        v = *(const float4*)(row +   0 + c4); *(float4*)&s_vh[w*AT_P+c4] = v;
        v = *(const float4*)(row + 128 + c4); *(float4*)&s_kh[w*AT_P+c4] = v;
        v = *(const float4*)(row + 384 + c4); *(float4*)&s_km[w*AT_P+c4] = v;
        v = *(const float4*)(row + 512 + c4); *(float4*)&s_vm[w*AT_P+c4] = v;
        const float* qrow = g_Y + (size_t)(b*1024 + w*32 + h)*640 + 256;
        v = *(const float4*)(qrow + c4);      *(float4*)&s_qt[w*AT_P+c4] = v;
    }
    __syncthreads();

    {
        const int wid = tid >> 5, lane = tid & 31;
        for (int i = 0; i < 16; i++){
            int c = wid + 8*i;
            float qv = s_qt[lane*AT_P + c];
            float s1 = s_kh[lane*AT_P + c] * qv;
            float mx = s1;
            #pragma unroll
            for (int o = 16; o; o >>= 1) mx = fmaxf(mx, __shfl_xor_sync(0xffffffffu, mx, o));
            float e1 = expf(s1 - mx), sm = e1;
            #pragma unroll
            for (int o = 16; o; o >>= 1) sm += __shfl_xor_sync(0xffffffffu, sm, o);
            s_vh[lane*AT_P + c] *= (e1 / sm);
            float s2 = qv * s_km[lane*AT_P + c];
            float mx2 = s2;
            #pragma unroll
            for (int o = 16; o; o >>= 1) mx2 = fmaxf(mx2, __shfl_xor_sync(0xffffffffu, mx2, o));
            float e2 = expf(s2 - mx2), sm2 = e2;
            #pragma unroll
            for (int o = 16; o; o >>= 1) sm2 += __shfl_xor_sync(0xffffffffu, sm2, o);
            s_vm[lane*AT_P + c] *= (e2 / sm2);
        }
    }
    __syncthreads();

    {
        __half* Ah = (__half*)(smemc + AT_AHI);
        __half* Al = (__half*)(smemc + AT_ALO);
        for (int q = tid; q < 32*64; q += 256){
            int r = q >> 6, c4 = (q & 63) * 4;
            float4 v = (c4 < 128) ? *(float4*)&s_vh[r*AT_P + c4]
                                  : *(float4*)&s_vm[r*AT_P + (c4 - 128)];
            __half2 h01 = __floats2half2_rn(v.x, v.y);
            __half2 h23 = __floats2half2_rn(v.z, v.w);
            __half2 l01 = __floats2half2_rn(v.x - __low2float(h01), v.y - __high2float(h01));
            __half2 l23 = __floats2half2_rn(v.z - __low2float(h23), v.w - __high2float(h23));
            int o = r*264 + c4;
            *(__half2*)(Ah + o) = h01; *(__half2*)(Ah + o + 2) = h23;
            *(__half2*)(Al + o) = l01; *(__half2*)(Al + o + 2) = l23;
        }
    }
    __syncthreads();

    const int wid = tid >> 5, lane = tid & 31;
    const int wm = wid >> 2, wn = wid & 3;
    const int m0 = wm*16, n0 = wn*32;
    const int l15 = lane & 15, lH = (lane >> 4) << 3;

    auto load_b = [&](int ch, int st){
        const int k0 = ch*32;
        #pragma unroll
        for (int q = tid; q < 1024; q += 256){
            int hh = q >> 9, e = q & 511, r = e >> 4, seg = e & 15;
            uint32_t dst = sbase + AT_B + (uint32_t)(st*17408 + hh*8704 + r*272 + seg*16);
            CPA(dst, (hh ? g_W8l : g_W8h) + (size_t)(k0 + r)*128 + seg*8);
        }
    };

    float d[4][4];
    #pragma unroll
    for (int a=0;a<4;a++){
        #pragma unroll
        for (int e=0;e<4;e++) d[a][e]=0.f; }

    load_b(0, 0); CPCOMMIT();
    load_b(1, 1); CPCOMMIT();

    for (int ch = 0; ch < 8; ch++){
        const int st = ch & 1;
        CPWAIT1();
        __syncthreads();
        #pragma unroll
        for (int ks = 0; ks < 2; ks++){
            const int kk = ch*32 + ks*16;
            uint32_t AH[4], AL[4], BH[2][4], BL[2][4];
            uint32_t ad = sbase + AT_AHI + (uint32_t)(((m0 + l15)*264 + kk + lH)*2);
            LDSM4(AH, ad);
            LDSM4(AL, ad + (AT_ALO - AT_AHI));
            #pragma unroll
            for (int bt = 0; bt < 2; bt++){
                uint32_t bd = sbase + AT_B + (uint32_t)(st*17408 + ((ks*16 + l15)*136 + n0 + bt*16 + lH)*2);
                LDSM4T(BH[bt], bd);
                LDSM4T(BL[bt], bd + 8704);
            }
            #pragma unroll
            for (int nj = 0; nj < 4; nj++){
                const int t = nj >> 1, o = (nj & 1)*2;
                MMA1(d[nj], AH[0],AH[1],AH[2],AH[3], BH[t][o], BH[t][o+1]);
                MMA1(d[nj], AL[0],AL[1],AL[2],AL[3], BH[t][o], BH[t][o+1]);
                MMA1(d[nj], AH[0],AH[1],AH[2],AH[3], BL[t][o], BL[t][o+1]);
            }
        }
        __syncthreads();
        if (ch + 2 < 8) load_b(ch + 2, st);
        CPCOMMIT();
    }
    CPWAIT0();
    __syncthreads();

    {
        float* sb = (float*)smemc;
        int rr = m0 + (lane>>2);
        #pragma unroll
        for (int nj = 0; nj < 4; nj++){
            int c = n0 + nj*8 + ((lane&3)<<1);
            sb[rr*132 + c]       = d[nj][0];
            sb[rr*132 + c + 1]   = d[nj][1];
            sb[(rr+8)*132 + c]   = d[nj][2];
            sb[(rr+8)*132 + c+1] = d[nj][3];
        }
        __syncthreads();
        for (int q = tid; q < 32*32; q += 256){
            int r = q >> 5, c4 = (q & 31) << 2;
            float4 v = *(float4*)&sb[r*132 + c4];
            float4 bv = *(const float4*)&b8[c4];
            v.x += bv.x; v.y += bv.y; v.z += bv.z; v.w += bv.w;
            store_hl(g_zfh, g_zfl, (size_t)(r0 + r)*128 + c4, v);
        }
    }
}

// ---------------- final gates (after conv7..9) -----------------------------
__global__ void k_final(int last){
    int idx = blockIdx.x*blockDim.x + threadIdx.x;
    int p = idx >> 5, c4 = (idx & 31) << 2;
    const float* y = g_g3 + (size_t)p*384 + c4;
    float4 OT = *(const float4*)(y);
    float4 GT = *(const float4*)(y + 128);
    float4 IT = *(const float4*)(y + 256);
    size_t o = (size_t)p*128 + c4;
    float4 M = *(float4*)(g_m + o);
    float4 mt, h;
    { float it = sigmoidf_(IT.x); mt.x = tanhf(GT.x)*it + (1.f-it)*M.x; h.x = sigmoidf_(OT.x)*mt.x; }
    { float it = sigmoidf_(IT.y); mt.y = tanhf(GT.y)*it + (1.f-it)*M.y; h.y = sigmoidf_(OT.y)*mt.y; }
    { float it = sigmoidf_(IT.z); mt.z = tanhf(GT.z)*it + (1.f-it)*M.z; h.z = sigmoidf_(OT.z)*mt.z; }
    { float it = sigmoidf_(IT.w); mt.w = tanhf(GT.w)*it + (1.f-it)*M.w; h.w = sigmoidf_(OT.w)*mt.w; }
    if (last){
        *(float4*)(g_H32 + o) = h;           // only consumer is k_outT at the end
    } else {
        *(float4*)(g_m + o) = mt;
        store_hl(g_mh, g_ml, o, mt);
        store_hl(g_HAh, g_HAl, o, h);
    }
}

// ---------------- layout transposes ----------------------------------------
#define SMEM_TR (128*132*4)
__global__ __launch_bounds__(256) void k_xT(const float* __restrict__ x){
    extern __shared__ float s[];
    int bid = blockIdx.x;
    int b = bid >> 7, t = (bid >> 3) & 15, n0 = (bid & 7) * 128;
    const float* src = x + (size_t)(b*16 + t)*128*1024;
    for (int q = threadIdx.x; q < 128*32; q += 256){
        int c = q >> 5, n4 = (q & 31) * 4;
        float4 v = *(const float4*)(src + (size_t)c*1024 + n0 + n4);
        s[(n4+0)*132 + c] = v.x; s[(n4+1)*132 + c] = v.y;
        s[(n4+2)*132 + c] = v.z; s[(n4+3)*132 + c] = v.w;
    }
    __syncthreads();
    size_t base = ((size_t)t*NPIX + b*1024 + n0)*128;
    for (int q = threadIdx.x; q < 128*32; q += 256){
        int n = q >> 5, c4 = (q & 31) * 4;
        store_hl(g_xTh, g_xTl, base + (size_t)n*128 + c4, *(float4*)&s[n*132 + c4]);
    }
}
__global__ __launch_bounds__(256) void k_init(const float* __restrict__ c0){
    extern __shared__ float s[];
    int b = blockIdx.x >> 3, n0 = (blockIdx.x & 7) * 128;
    const float* src = c0 + (size_t)b*128*1024;
    for (int q = threadIdx.x; q < 128*32; q += 256){
        int c = q >> 5, n4 = (q & 31) * 4;
        float4 v = *(const float4*)(src + (size_t)c*1024 + n0 + n4);
        s[(n4+0)*132 + c] = v.x; s[(n4+1)*132 + c] = v.y;
        s[(n4+2)*132 + c] = v.z; s[(n4+3)*132 + c] = v.w;
    }
    __syncthreads();
    size_t base = (size_t)(b*1024 + n0)*128;
    float4 zz = {0.f,0.f,0.f,0.f};
    for (int q = threadIdx.x; q < 128*32; q += 256){
        int n = q >> 5, c4 = (q & 31) * 4;
        size_t o = base + (size_t)n*128 + c4;
        *(float4*)(g_C + o) = *(float4*)&s[n*132 + c4];
        *(float4*)(g_m + o) = zz;
        store_hl(g_HAh, g_HAl, o, zz);
        store_hl(g_mh, g_ml, o, zz);
    }
}
__global__ __launch_bounds__(256) void k_outT(float* __restrict__ out){
    extern __shared__ float s[];
    int b = blockIdx.x >> 3, n0 = (blockIdx.x & 7) * 128;
    const float* src = g_H32 + (size_t)(b*1024 + n0)*128;
    for (int q = threadIdx.x; q < 128*32; q += 256){
        int n = q >> 5, c4 = (q & 31) * 4;
        float4 v = *(const float4*)(src + (size_t)n*128 + c4);
        s[(c4+0)*132 + n] = v.x; s[(c4+1)*132 + n] = v.y;
        s[(c4+2)*132 + n] = v.z; s[(c4+3)*132 + n] = v.w;
    }
    __syncthreads();
    float* dst = out + (size_t)b*128*1024;
    for (int q = threadIdx.x; q < 128*32; q += 256){
        int c = q >> 5, n4 = (q & 31) * 4;
        *(float4*)(dst + (size_t)c*1024 + n0 + n4) = *(float4*)&s[c*132 + n4];
    }
}

// ---------------------------------------------------------------------------
extern "C" void kernel_launch(void* const* d_in, const int* in_sizes, int n_in,
                              void* d_out, int out_size)
{
    const float* x  = (const float*)d_in[0];
    const float* c0 = (const float*)d_in[1];
    const float* W5 = (const float*)d_in[2];
    const float* b5 = (const float*)d_in[3];
    const float* W8 = (const float*)d_in[4];
    const float* b8 = (const float*)d_in[5];
    float* out = (float*)d_out;

    cudaFuncSetAttribute(gemm2,      cudaFuncAttributeMaxDynamicSharedMemorySize, SMEM_G2);
    cudaFuncSetAttribute(gemm_step1, cudaFuncAttributeMaxDynamicSharedMemorySize, SMEM_G2);
    cudaFuncSetAttribute(attn6, cudaFuncAttributeMaxDynamicSharedMemorySize, SMEM_AT);
    cudaFuncSetAttribute(k_xT,   cudaFuncAttributeMaxDynamicSharedMemorySize, SMEM_TR);
    cudaFuncSetAttribute(k_init, cudaFuncAttributeMaxDynamicSharedMemorySize, SMEM_TR);
    cudaFuncSetAttribute(k_outT, cudaFuncAttributeMaxDynamicSharedMemorySize, SMEM_TR);

    float *pY, *pG3;
    __half *pHBh,*pHBl,*pzfh,*pzfl,*pxTh,*pxTl,*pW5h,*pW5l,*pW8h,*pW8l;
    cudaGetSymbolAddress((void**)&pY,  g_Y);
    cudaGetSymbolAddress((void**)&pG3, g_g3);
    cudaGetSymbolAddress((void**)&pHBh,g_HBh); cudaGetSymbolAddress((void**)&pHBl,g_HBl);
    cudaGetSymbolAddress((void**)&pzfh,g_zfh); cudaGetSymbolAddress((void**)&pzfl,g_zfl);
    cudaGetSymbolAddress((void**)&pxTh,g_xTh); cudaGetSymbolAddress((void**)&pxTl,g_xTl);
    cudaGetSymbolAddress((void**)&pW5h,g_W5h); cudaGetSymbolAddress((void**)&pW5l,g_W5l);
    cudaGetSymbolAddress((void**)&pW8h,g_W8h); cudaGetSymbolAddress((void**)&pW8l,g_W8l);

    k_wprep<<<1860, 256>>>(W5, W8, b8);
    k_xT<<<2048, 256, SMEM_TR>>>(x);
    k_init<<<128, 256, SMEM_TR>>>(c0);

    for (int t = 0; t < TT; t++){
        const size_t xo = (size_t)t*NPIX*128;
        // conv10..13 + LSTM gates (H_A -> H_B, C update) || conv4..5 on m -> Y[384:640]
        gemm_step1<<<dim3(256,6), 256, SMEM_G2>>>(pxTh + xo, pxTl + xo, b5);
        // conv1..3 on H_B -> Y[0:384]
        gemm2<<<dim3(256,3), 256, SMEM_G2>>>(pHBh, pHBl, pHBh, pHBl, 128,
            128, pW5h, pW5l, b5, pY, 640, 0);
        // attention + conv6 -> z (fp16 hi/lo)
        attn6<<<512, 256, SMEM_AT>>>(b8);
        // conv7..9 on [H_B | z] -> g3
        gemm2<<<dim3(256,3), 256, SMEM_G2>>>(pHBh, pHBl, pzfh, pzfl, 128,
            256, pW8h + (size_t)1*256*128, pW8l + (size_t)1*256*128, b8 + 128,
            pG3, 384, 0);
        // final gates: m update, H -> H_A (H32 only written at the last step)
        k_final<<<2048, 256>>>(t == TT-1 ? 1 : 0);
    }
    k_outT<<<128, 256, SMEM_TR>>>(out);
}